// round 7
// baseline (speedup 1.0000x reference)
#include <cuda_runtime.h>
#include <math.h>
#include <stdint.h>

// ============================================================================
// TPForth: e3nn-style tensor product, B x (x1[156], x2[9], w[7128]) -> out[156]
// Persistent kernel: 148 blocks (1/SM), 320 threads = 2 teams x 160.
// 6-stage x 1-row TMA ring (175KB smem): >=4 copies always queued per SM so
// DRAM demand never gaps. Contiguous row partition for HBM row locality.
// ============================================================================

#define WTOT 7128
#define XW   156
#define STAGES 6
#define TEAM_THREADS 160

// Weight sub-matrix offsets (floats within a row), shapes (U, Wd):
//  w00  @    0 (48,48)   w01  @ 2304 (48,10)   w10  @ 2784 (10,10)
//  w110 @ 2884 (10,48)   w112 @ 3364 (10,10)   w12  @ 3464 (10,10)
//  w20  @ 3564 (10,10)   w211 @ 3664 (10,10)   w213 @ 3764 (10,48)
//  w22  @ 4244 (10,10)   w30  @ 4344 (48,48)   w31  @ 6648 (48,10)

__device__ float d_w3j111[27];
__device__ float d_w3j121[45];

// ---------------------------------------------------------------------------
// Parallel fp32 Wigner-3j init (one element per thread).
// ---------------------------------------------------------------------------
struct CF { float r, i; };
__device__ __forceinline__ CF cmulf(CF a, CF b) {
    CF c; c.r = a.r*b.r - a.i*b.i; c.i = a.r*b.i + a.i*b.r; return c;
}

__device__ void change_basis_f(int l, CF* q) {
    int n = 2*l + 1;
    for (int a = 0; a < n*n; a++) { q[a].r = 0.f; q[a].i = 0.f; }
    const float rs2 = 0.70710678118654752f;
    for (int m = -l; m < 0; m++) {
        q[(l+m)*n + (l - m)].r =  rs2;
        q[(l+m)*n + (l + m)].i = -rs2;
    }
    q[l*n + l].r = 1.f;
    for (int m = 1; m <= l; m++) {
        float s = (m & 1) ? -1.f : 1.f;
        q[(l+m)*n + (l+m)].r = s * rs2;
        q[(l+m)*n + (l-m)].i = s * rs2;
    }
    CF ph;
    switch (l & 3) {
        case 0: ph.r = 1;  ph.i = 0;  break;
        case 1: ph.r = 0;  ph.i = -1; break;
        case 2: ph.r = -1; ph.i = 0;  break;
        default: ph.r = 0; ph.i = 1;  break;
    }
    for (int a = 0; a < n*n; a++) q[a] = cmulf(q[a], ph);
}

__device__ float cg_f(int j1, int j2, int j3, int m1, int m2, int m3,
                      const float* ft) {
    int vmin = -j1 + j2 + m3;
    if (-j1 + m1 > vmin) vmin = -j1 + m1;
    if (0 > vmin) vmin = 0;
    int vmax = j2 + j3 + m1;
    if (j3 - j1 + j2 < vmax) vmax = j3 - j1 + j2;
    if (j3 + m3 < vmax) vmax = j3 + m3;
    float C = sqrtf((2.f*j3 + 1.f) * ft[j3+j1-j2] * ft[j3-j1+j2] * ft[j1+j2-j3]
                    * ft[j3+m3] * ft[j3-m3]
                    / (ft[j1+j2+j3+1] * ft[j1-m1] * ft[j1+m1]
                       * ft[j2-m2] * ft[j2+m2]));
    float S = 0.f;
    for (int v = vmin; v <= vmax; v++) {
        float sgn = ((v + j2 + m2) & 1) ? -1.f : 1.f;
        S += sgn * ft[j2+j3+m1-v] * ft[j1-m1+v]
             / (ft[v] * ft[j3-j1+j2-v] * ft[j3+m3-v] * ft[v+j1-j2-m3]);
    }
    return C * S;
}

__device__ float w3j_elem(int l1, int l2, int l3, int j, int l, int m,
                          const float* ft) {
    int n1 = 2*l1+1, n2 = 2*l2+1, n3 = 2*l3+1;
    CF Q1[25], Q2[25], Q3[25];
    change_basis_f(l1, Q1);
    change_basis_f(l2, Q2);
    change_basis_f(l3, Q3);
    float acc = 0.f;
    for (int i = 0; i < n1; i++) {
        for (int k = 0; k < n2; k++) {
            int m3v = (i - l1) + (k - l2);
            if (m3v < -l3 || m3v > l3) continue;
            int nn = l3 + m3v;
            float cgv = cg_f(l1, l2, l3, i - l1, k - l2, m3v, ft);
            CF t = cmulf(Q1[i*n1 + j], Q2[k*n2 + l]);
            CF q3c; q3c.r = Q3[nn*n3 + m].r; q3c.i = -Q3[nn*n3 + m].i;
            t = cmulf(t, q3c);
            acc += t.r * cgv;
        }
    }
    return acc;
}

__global__ void init_w3j_kernel() {
    __shared__ float s111[27], s121[45];
    __shared__ float inv111, inv121;
    int tid = threadIdx.x;
    float ft[8];
    ft[0] = 1.f;
    for (int k = 1; k < 8; k++) ft[k] = ft[k-1] * (float)k;

    if (tid < 27) {
        int j = tid / 9, rem = tid % 9, l = rem / 3, m = rem % 3;
        s111[tid] = w3j_elem(1, 1, 1, j, l, m, ft);
    } else if (tid >= 32 && tid < 77) {
        int idx = tid - 32;
        int j = idx / 15, rem = idx % 15, l = rem / 3, m = rem % 3;
        s121[idx] = w3j_elem(1, 2, 1, j, l, m, ft);
    }
    __syncthreads();
    if (tid == 0) {
        float s = 0.f;
        for (int a = 0; a < 27; a++) s += s111[a] * s111[a];
        inv111 = rsqrtf(s);
    }
    if (tid == 1) {
        float s = 0.f;
        for (int a = 0; a < 45; a++) s += s121[a] * s121[a];
        inv121 = rsqrtf(s);
    }
    __syncthreads();
    if (tid < 27) d_w3j111[tid] = s111[tid] * inv111;
    if (tid >= 32 && tid < 77) d_w3j121[tid - 32] = s121[tid - 32] * inv121;
}

// ---------------------------------------------------------------------------
__device__ __forceinline__ uint32_t smem_u32(const void* p) {
    uint32_t a;
    asm("{ .reg .u64 t; cvta.to.shared.u64 t, %1; cvt.u32.u64 %0, t; }"
        : "=r"(a) : "l"(p));
    return a;
}

struct __align__(16) StageBuf {
    float sw[WTOT];
    float sx1[XW];
};

struct __align__(16) TeamAux {
    float sx2[12];
    float d110[10], d213[10];
    float c112[30], c12[30], c211[30], c22[30];
};

struct __align__(128) SmemLayout {
    StageBuf st[STAGES];           // 6 x 29136 B = 174816
    TeamAux  aux[2];
    float sj1[27], sj2[45];
    uint64_t mbar[STAGES];
};

__device__ __forceinline__ void issue_stage_tma(
    SmemLayout* S, int s, const float* w, const float* x1, size_t row)
{
    uint32_t mb = smem_u32(&S->mbar[s]);
    const uint32_t wb = (uint32_t)(WTOT * 4);
    const uint32_t xb = (uint32_t)(XW * 4);
    asm volatile("fence.proxy.async.shared::cta;" ::: "memory");
    asm volatile("mbarrier.arrive.expect_tx.shared.b64 _, [%0], %1;"
                 :: "r"(mb), "r"(wb + xb) : "memory");
    asm volatile(
        "cp.async.bulk.shared::cluster.global.mbarrier::complete_tx::bytes "
        "[%0], [%1], %2, [%3];"
        :: "r"(smem_u32(S->st[s].sw)), "l"(w + row * WTOT), "r"(wb), "r"(mb)
        : "memory");
    asm volatile(
        "cp.async.bulk.shared::cluster.global.mbarrier::complete_tx::bytes "
        "[%0], [%1], %2, [%3];"
        :: "r"(smem_u32(S->st[s].sx1)), "l"(x1 + row * XW), "r"(xb), "r"(mb)
        : "memory");
}

__device__ __forceinline__ void mbar_wait(uint32_t mb, uint32_t parity) {
    uint32_t done;
    do {
        asm volatile(
            "{\n .reg .pred p;\n"
            " mbarrier.try_wait.parity.acquire.cta.shared::cta.b64 p, [%1], %2, 0x989680;\n"
            " selp.b32 %0, 1, 0, p;\n}"
            : "=r"(done) : "r"(mb), "r"(parity) : "memory");
    } while (!done);
}

__device__ __forceinline__ void team_bar(int team) {
    asm volatile("bar.sync %0, %1;" :: "r"(team + 1), "r"(TEAM_THREADS)
                 : "memory");
}

__global__ __launch_bounds__(320, 1) void tp_kernel(
    const float* __restrict__ x1,
    const float* __restrict__ x2,
    const float* __restrict__ w,
    float* __restrict__ out,
    int nrows_total)
{
    extern __shared__ __align__(128) char smem_raw[];
    SmemLayout* S = reinterpret_cast<SmemLayout*>(smem_raw);

    const int tid  = threadIdx.x;
    const int team = tid / TEAM_THREADS;     // 0 or 1
    const int lt   = tid - team * TEAM_THREADS;
    const int G    = gridDim.x;
    const int b    = blockIdx.x;

    // Contiguous row partition: block b owns rows [start, start+cnt)
    const int per   = (nrows_total + G - 1) / G;
    const int start = b * per;
    int cnt = nrows_total - start;
    if (cnt < 0) cnt = 0;
    if (cnt > per) cnt = per;

    // ---- Prologue: init mbars, fill stages 0..5 ----
    if (tid == 0) {
        #pragma unroll
        for (int s = 0; s < STAGES; s++) {
            asm volatile("mbarrier.init.shared.b64 [%0], %1;"
                         :: "r"(smem_u32(&S->mbar[s])), "r"(1) : "memory");
        }
        for (int k = 0; k < STAGES && k < cnt; k++)
            issue_stage_tma(S, k, w, x1, (size_t)(start + k));
    }
    if (tid >= 64 && tid < 91)        S->sj1[tid - 64]  = d_w3j111[tid - 64];
    else if (tid >= 96 && tid < 141)  S->sj2[tid - 96]  = d_w3j121[tid - 96];

    // x2 lanes: team-local threads 144..152 load the row's 9 x2 floats
    const bool x2lane = (lt >= 144 && lt < 153);
    const int  x2o = lt - 144;

    // Hoisted per-thread output indices
    int m_case, m_wI = 0, m_k = 0;
    if (lt < 48)       { m_case = 0; m_wI = lt; }
    else if (lt < 78)  { m_case = 1; m_wI = (lt-48)/3; m_k = (lt-48)%3; }
    else if (lt < 108) { m_case = 2; m_wI = (lt-78)/3; m_k = (lt-78)%3; }
    else if (lt < 156) { m_case = 3; m_wI = lt - 108; }
    else               { m_case = 4; }

    const float NORM_0E = 0.13130643285972254f;  // sqrt(1/58)
    const float NORM_1O = 0.19611613513818404f;  // sqrt(3/78)
    const float NORM_1E = 0.19611613513818404f;
    const float NORM_0O = 0.13130643285972254f;
    const float RS3     = 0.57735026918962576f;

    TeamAux* A = &S->aux[team];

    __syncthreads();   // mbar init + sj visible to both teams

    // ---- Team loop: team t handles iterations i = t, t+2, t+4, ... ----
    for (int i = team; i < cnt; i += 2) {
        const int s = i % STAGES;            // stage owner: same team forever
        const uint32_t parity = (uint32_t)((i / STAGES) & 1);
        const size_t row = (size_t)(start + i);

        // issue x2 LDG before the wait (latency hides under TMA delivery)
        float x2reg = 0.f;
        if (x2lane) x2reg = x2[row * 9 + x2o];

        mbar_wait(smem_u32(&S->mbar[s]), parity);

        if (x2lane) A->sx2[x2o] = x2reg;
        team_bar(team);

        const StageBuf* st = &S->st[s];
        const float* px1 = st->sx1;
        const float* px2 = A->sx2;

        // ---- Aux coefficients ----
        if (lt < 10) {
            float v = 0.f;
            #pragma unroll
            for (int q = 0; q < 3; q++) v += px1[48 + lt*3 + q] * px2[1 + q];
            A->d110[lt] = v;
        } else if (lt < 20) {
            int u = lt - 10; float v = 0.f;
            #pragma unroll
            for (int q = 0; q < 3; q++) v += px1[78 + u*3 + q] * px2[1 + q];
            A->d213[u] = v;
        } else if (lt < 50) {
            int t = lt - 20, u = t/3, k = t%3; float v = 0.f;
            #pragma unroll
            for (int q = 0; q < 3; q++)
                #pragma unroll
                for (int j = 0; j < 3; j++)
                    v += px1[48 + u*3 + q] * px2[1 + j] * S->sj1[q*9 + j*3 + k];
            A->c112[t] = v;
        } else if (lt < 80) {
            int t = lt - 50, u = t/3, k = t%3; float v = 0.f;
            #pragma unroll
            for (int q = 0; q < 3; q++)
                #pragma unroll
                for (int j = 0; j < 5; j++)
                    v += px1[48 + u*3 + q] * px2[4 + j] * S->sj2[q*15 + j*3 + k];
            A->c12[t] = v;
        } else if (lt < 110) {
            int t = lt - 80, u = t/3, k = t%3; float v = 0.f;
            #pragma unroll
            for (int q = 0; q < 3; q++)
                #pragma unroll
                for (int j = 0; j < 3; j++)
                    v += px1[78 + u*3 + q] * px2[1 + j] * S->sj1[q*9 + j*3 + k];
            A->c211[t] = v;
        } else if (lt < 140) {
            int t = lt - 110, u = t/3, k = t%3; float v = 0.f;
            #pragma unroll
            for (int q = 0; q < 3; q++)
                #pragma unroll
                for (int j = 0; j < 5; j++)
                    v += px1[78 + u*3 + q] * px2[4 + j] * S->sj2[q*15 + j*3 + k];
            A->c22[t] = v;
        }
        team_bar(team);

        // ---- Main compute: one thread per output element ----
        if (m_case < 4) {
            const float* sw = st->sw;
            float* orow = out + row * XW;

            if (m_case == 0) {
                float a = 0.f;
                #pragma unroll 8
                for (int u = 0; u < 48; u++) a += px1[u] * sw[u*48 + m_wI];
                float bb = 0.f;
                #pragma unroll
                for (int u = 0; u < 10; u++) bb += A->d110[u] * sw[2884 + u*48 + m_wI];
                orow[lt] = NORM_0E * (a * px2[0] + RS3 * bb);
            } else if (m_case == 1) {
                float t01 = 0.f;
                #pragma unroll 8
                for (int u = 0; u < 48; u++) t01 += px1[u] * sw[2304 + u*10 + m_wI];
                float a10 = 0.f, a12 = 0.f, a211 = 0.f;
                #pragma unroll
                for (int u = 0; u < 10; u++) {
                    a10  += px1[48 + u*3 + m_k] * sw[2784 + u*10 + m_wI];
                    a12  += A->c12[u*3 + m_k]   * sw[3464 + u*10 + m_wI];
                    a211 += A->c211[u*3 + m_k]  * sw[3664 + u*10 + m_wI];
                }
                orow[lt] = NORM_1O * (RS3 * (t01 * px2[1 + m_k] + px2[0] * a10) + a12 + a211);
            } else if (m_case == 2) {
                float t31 = 0.f;
                #pragma unroll 8
                for (int u = 0; u < 48; u++) t31 += px1[108 + u] * sw[6648 + u*10 + m_wI];
                float a112 = 0.f, a20 = 0.f, a22 = 0.f;
                #pragma unroll
                for (int u = 0; u < 10; u++) {
                    a112 += A->c112[u*3 + m_k] * sw[3364 + u*10 + m_wI];
                    a20  += px1[78 + u*3 + m_k] * sw[3564 + u*10 + m_wI];
                    a22  += A->c22[u*3 + m_k]  * sw[4244 + u*10 + m_wI];
                }
                orow[lt] = NORM_1E * (a112 + RS3 * (px2[0] * a20 + t31 * px2[1 + m_k]) + a22);
            } else {
                float a = 0.f;
                #pragma unroll
                for (int u = 0; u < 10; u++) a += A->d213[u] * sw[3764 + u*48 + m_wI];
                float bb = 0.f;
                #pragma unroll 8
                for (int u = 0; u < 48; u++) bb += px1[108 + u] * sw[4344 + u*48 + m_wI];
                orow[lt] = NORM_0O * (RS3 * a + bb * px2[0]);
            }
        }

        team_bar(team);   // team done reading stage s

        // ---- Reissue stage s for iteration i+STAGES (same team owns it) ----
        if (lt == 0 && i + STAGES < cnt)
            issue_stage_tma(S, s, w, x1, (size_t)(start + i + STAGES));
    }
}

// ---------------------------------------------------------------------------
extern "C" void kernel_launch(void* const* d_in, const int* in_sizes, int n_in,
                              void* d_out, int out_size)
{
    const float* x1 = (const float*)d_in[0];
    const float* x2 = (const float*)d_in[1];
    const float* w  = (const float*)d_in[2];
    float* out = (float*)d_out;

    int B = in_sizes[1] / 9;
    int smem_bytes = (int)sizeof(SmemLayout);

    cudaFuncSetAttribute(tp_kernel,
                         cudaFuncAttributeMaxDynamicSharedMemorySize, smem_bytes);

    init_w3j_kernel<<<1, 128>>>();
    tp_kernel<<<148, 320, smem_bytes>>>(x1, x2, w, out, B);
}

// round 8
// speedup vs baseline: 1.1838x; 1.1838x over previous
#include <cuda_runtime.h>
#include <math.h>
#include <stdint.h>

// ============================================================================
// TPForth: e3nn-style tensor product, B x (x1[156], x2[9], w[7128]) -> out[156]
// Grid 444 = 3 blocks/SM, 320 threads each, 2-stage x 1-row TMA ring (58.5KB).
// Per SM: 6 rows of copies in flight => continuous DRAM demand. All 320
// threads compute one row (48-reductions split across lane pairs + shfl).
// ============================================================================

#define WTOT 7128
#define XW   156
#define NSTAGE 2

// Weight sub-matrix offsets (floats within a row), shapes (U, Wd):
//  w00  @    0 (48,48)   w01  @ 2304 (48,10)   w10  @ 2784 (10,10)
//  w110 @ 2884 (10,48)   w112 @ 3364 (10,10)   w12  @ 3464 (10,10)
//  w20  @ 3564 (10,10)   w211 @ 3664 (10,10)   w213 @ 3764 (10,48)
//  w22  @ 4244 (10,10)   w30  @ 4344 (48,48)   w31  @ 6648 (48,10)

__device__ float d_w3j111[27];
__device__ float d_w3j121[45];

// ---------------------------------------------------------------------------
// Parallel fp32 Wigner-3j init (one element per thread).
// ---------------------------------------------------------------------------
struct CF { float r, i; };
__device__ __forceinline__ CF cmulf(CF a, CF b) {
    CF c; c.r = a.r*b.r - a.i*b.i; c.i = a.r*b.i + a.i*b.r; return c;
}

__device__ void change_basis_f(int l, CF* q) {
    int n = 2*l + 1;
    for (int a = 0; a < n*n; a++) { q[a].r = 0.f; q[a].i = 0.f; }
    const float rs2 = 0.70710678118654752f;
    for (int m = -l; m < 0; m++) {
        q[(l+m)*n + (l - m)].r =  rs2;
        q[(l+m)*n + (l + m)].i = -rs2;
    }
    q[l*n + l].r = 1.f;
    for (int m = 1; m <= l; m++) {
        float s = (m & 1) ? -1.f : 1.f;
        q[(l+m)*n + (l+m)].r = s * rs2;
        q[(l+m)*n + (l-m)].i = s * rs2;
    }
    CF ph;
    switch (l & 3) {
        case 0: ph.r = 1;  ph.i = 0;  break;
        case 1: ph.r = 0;  ph.i = -1; break;
        case 2: ph.r = -1; ph.i = 0;  break;
        default: ph.r = 0; ph.i = 1;  break;
    }
    for (int a = 0; a < n*n; a++) q[a] = cmulf(q[a], ph);
}

__device__ float cg_f(int j1, int j2, int j3, int m1, int m2, int m3,
                      const float* ft) {
    int vmin = -j1 + j2 + m3;
    if (-j1 + m1 > vmin) vmin = -j1 + m1;
    if (0 > vmin) vmin = 0;
    int vmax = j2 + j3 + m1;
    if (j3 - j1 + j2 < vmax) vmax = j3 - j1 + j2;
    if (j3 + m3 < vmax) vmax = j3 + m3;
    float C = sqrtf((2.f*j3 + 1.f) * ft[j3+j1-j2] * ft[j3-j1+j2] * ft[j1+j2-j3]
                    * ft[j3+m3] * ft[j3-m3]
                    / (ft[j1+j2+j3+1] * ft[j1-m1] * ft[j1+m1]
                       * ft[j2-m2] * ft[j2+m2]));
    float S = 0.f;
    for (int v = vmin; v <= vmax; v++) {
        float sgn = ((v + j2 + m2) & 1) ? -1.f : 1.f;
        S += sgn * ft[j2+j3+m1-v] * ft[j1-m1+v]
             / (ft[v] * ft[j3-j1+j2-v] * ft[j3+m3-v] * ft[v+j1-j2-m3]);
    }
    return C * S;
}

__device__ float w3j_elem(int l1, int l2, int l3, int j, int l, int m,
                          const float* ft) {
    int n1 = 2*l1+1, n2 = 2*l2+1, n3 = 2*l3+1;
    CF Q1[25], Q2[25], Q3[25];
    change_basis_f(l1, Q1);
    change_basis_f(l2, Q2);
    change_basis_f(l3, Q3);
    float acc = 0.f;
    for (int i = 0; i < n1; i++) {
        for (int k = 0; k < n2; k++) {
            int m3v = (i - l1) + (k - l2);
            if (m3v < -l3 || m3v > l3) continue;
            int nn = l3 + m3v;
            float cgv = cg_f(l1, l2, l3, i - l1, k - l2, m3v, ft);
            CF t = cmulf(Q1[i*n1 + j], Q2[k*n2 + l]);
            CF q3c; q3c.r = Q3[nn*n3 + m].r; q3c.i = -Q3[nn*n3 + m].i;
            t = cmulf(t, q3c);
            acc += t.r * cgv;
        }
    }
    return acc;
}

__global__ void init_w3j_kernel() {
    __shared__ float s111[27], s121[45];
    __shared__ float inv111, inv121;
    int tid = threadIdx.x;
    float ft[8];
    ft[0] = 1.f;
    for (int k = 1; k < 8; k++) ft[k] = ft[k-1] * (float)k;

    if (tid < 27) {
        int j = tid / 9, rem = tid % 9, l = rem / 3, m = rem % 3;
        s111[tid] = w3j_elem(1, 1, 1, j, l, m, ft);
    } else if (tid >= 32 && tid < 77) {
        int idx = tid - 32;
        int j = idx / 15, rem = idx % 15, l = rem / 3, m = rem % 3;
        s121[idx] = w3j_elem(1, 2, 1, j, l, m, ft);
    }
    __syncthreads();
    if (tid == 0) {
        float s = 0.f;
        for (int a = 0; a < 27; a++) s += s111[a] * s111[a];
        inv111 = rsqrtf(s);
    }
    if (tid == 1) {
        float s = 0.f;
        for (int a = 0; a < 45; a++) s += s121[a] * s121[a];
        inv121 = rsqrtf(s);
    }
    __syncthreads();
    if (tid < 27) d_w3j111[tid] = s111[tid] * inv111;
    if (tid >= 32 && tid < 77) d_w3j121[tid - 32] = s121[tid - 32] * inv121;
}

// ---------------------------------------------------------------------------
__device__ __forceinline__ uint32_t smem_u32(const void* p) {
    uint32_t a;
    asm("{ .reg .u64 t; cvta.to.shared.u64 t, %1; cvt.u32.u64 %0, t; }"
        : "=r"(a) : "l"(p));
    return a;
}

struct __align__(16) StageBuf {
    float sw[WTOT];
    float sx1[XW];
};

struct __align__(128) SmemLayout {
    StageBuf st[NSTAGE];           // 2 x 29136 B
    float sx2[12];
    float d110[10], d213[10];
    float c112[30], c12[30], c211[30], c22[30];
    float sj1[27], sj2[45];
    uint64_t mbar[NSTAGE];
};

__device__ __forceinline__ void issue_stage_tma(
    SmemLayout* S, int s, const float* w, const float* x1, size_t row)
{
    uint32_t mb = smem_u32(&S->mbar[s]);
    const uint32_t wb = (uint32_t)(WTOT * 4);
    const uint32_t xb = (uint32_t)(XW * 4);
    asm volatile("fence.proxy.async.shared::cta;" ::: "memory");
    asm volatile("mbarrier.arrive.expect_tx.shared.b64 _, [%0], %1;"
                 :: "r"(mb), "r"(wb + xb) : "memory");
    asm volatile(
        "cp.async.bulk.shared::cluster.global.mbarrier::complete_tx::bytes "
        "[%0], [%1], %2, [%3];"
        :: "r"(smem_u32(S->st[s].sw)), "l"(w + row * WTOT), "r"(wb), "r"(mb)
        : "memory");
    asm volatile(
        "cp.async.bulk.shared::cluster.global.mbarrier::complete_tx::bytes "
        "[%0], [%1], %2, [%3];"
        :: "r"(smem_u32(S->st[s].sx1)), "l"(x1 + row * XW), "r"(xb), "r"(mb)
        : "memory");
}

__device__ __forceinline__ void mbar_wait(uint32_t mb, uint32_t parity) {
    uint32_t done;
    do {
        asm volatile(
            "{\n .reg .pred p;\n"
            " mbarrier.try_wait.parity.acquire.cta.shared::cta.b64 p, [%1], %2, 0x989680;\n"
            " selp.b32 %0, 1, 0, p;\n}"
            : "=r"(done) : "r"(mb), "r"(parity) : "memory");
    } while (!done);
}

__global__ __launch_bounds__(320, 3) void tp_kernel(
    const float* __restrict__ x1,
    const float* __restrict__ x2,
    const float* __restrict__ w,
    float* __restrict__ out,
    int nrows_total)
{
    extern __shared__ __align__(128) char smem_raw[];
    SmemLayout* S = reinterpret_cast<SmemLayout*>(smem_raw);

    const int tid = threadIdx.x;
    const int G   = gridDim.x;
    const int b   = blockIdx.x;
    const int cnt = (nrows_total > b) ? (nrows_total - b + G - 1) / G : 0;

    // Split-reduction mapping: lane pair (h=0,1) per output element
    const int lt = tid >> 1;        // output element 0..159
    const int h  = tid & 1;         // reduction half
    const int ub = h * 24;          // 48-loop base
    const int vb = h * 5;           // 10-loop base

    // ---- Prologue: init mbars, fill both stages ----
    if (tid == 0) {
        #pragma unroll
        for (int s = 0; s < NSTAGE; s++) {
            asm volatile("mbarrier.init.shared.b64 [%0], %1;"
                         :: "r"(smem_u32(&S->mbar[s])), "r"(1) : "memory");
        }
        for (int k = 0; k < NSTAGE && k < cnt; k++)
            issue_stage_tma(S, k, w, x1, (size_t)b + (size_t)k * G);
    }
    if (tid >= 160 && tid < 187)       S->sj1[tid - 160] = d_w3j111[tid - 160];
    else if (tid >= 192 && tid < 237)  S->sj2[tid - 192] = d_w3j121[tid - 192];

    // x2 lanes: threads 288..296 (warp 9) handle the row's 9 x2 floats
    const bool x2lane = (tid >= 288 && tid < 297);
    const int  x2o = tid - 288;

    // Hoisted per-thread output indices
    int m_case, m_wI = 0, m_k = 0;
    if (lt < 48)       { m_case = 0; m_wI = lt; }
    else if (lt < 78)  { m_case = 1; m_wI = (lt-48)/3; m_k = (lt-48)%3; }
    else if (lt < 108) { m_case = 2; m_wI = (lt-78)/3; m_k = (lt-78)%3; }
    else if (lt < 156) { m_case = 3; m_wI = lt - 108; }
    else               { m_case = 4; }

    const float NORM_0E = 0.13130643285972254f;  // sqrt(1/58)
    const float NORM_1O = 0.19611613513818404f;  // sqrt(3/78)
    const float NORM_1E = 0.19611613513818404f;
    const float NORM_0O = 0.13130643285972254f;
    const float RS3     = 0.57735026918962576f;

    __syncthreads();   // mbar init + sj visible

    for (int i = 0; i < cnt; ++i) {
        const int s = i & 1;
        const uint32_t parity = (uint32_t)((i >> 1) & 1);
        const size_t row = (size_t)b + (size_t)i * G;

        // x2 LDG issued before the wait (latency hides under TMA delivery)
        float x2reg = 0.f;
        if (x2lane) x2reg = x2[row * 9 + x2o];

        mbar_wait(smem_u32(&S->mbar[s]), parity);

        if (x2lane) S->sx2[x2o] = x2reg;
        __syncthreads();

        const StageBuf* st = &S->st[s];
        const float* px1 = st->sx1;
        const float* px2 = S->sx2;

        // ---- Aux coefficients (threads 0..139 directly) ----
        if (tid < 10) {
            float v = 0.f;
            #pragma unroll
            for (int q = 0; q < 3; q++) v += px1[48 + tid*3 + q] * px2[1 + q];
            S->d110[tid] = v;
        } else if (tid < 20) {
            int u = tid - 10; float v = 0.f;
            #pragma unroll
            for (int q = 0; q < 3; q++) v += px1[78 + u*3 + q] * px2[1 + q];
            S->d213[u] = v;
        } else if (tid < 50) {
            int t = tid - 20, u = t/3, k = t%3; float v = 0.f;
            #pragma unroll
            for (int q = 0; q < 3; q++)
                #pragma unroll
                for (int j = 0; j < 3; j++)
                    v += px1[48 + u*3 + q] * px2[1 + j] * S->sj1[q*9 + j*3 + k];
            S->c112[t] = v;
        } else if (tid < 80) {
            int t = tid - 50, u = t/3, k = t%3; float v = 0.f;
            #pragma unroll
            for (int q = 0; q < 3; q++)
                #pragma unroll
                for (int j = 0; j < 5; j++)
                    v += px1[48 + u*3 + q] * px2[4 + j] * S->sj2[q*15 + j*3 + k];
            S->c12[t] = v;
        } else if (tid < 110) {
            int t = tid - 80, u = t/3, k = t%3; float v = 0.f;
            #pragma unroll
            for (int q = 0; q < 3; q++)
                #pragma unroll
                for (int j = 0; j < 3; j++)
                    v += px1[78 + u*3 + q] * px2[1 + j] * S->sj1[q*9 + j*3 + k];
            S->c211[t] = v;
        } else if (tid < 140) {
            int t = tid - 110, u = t/3, k = t%3; float v = 0.f;
            #pragma unroll
            for (int q = 0; q < 3; q++)
                #pragma unroll
                for (int j = 0; j < 5; j++)
                    v += px1[78 + u*3 + q] * px2[4 + j] * S->sj2[q*15 + j*3 + k];
            S->c22[t] = v;
        }
        __syncthreads();

        // ---- Main compute: lane-pair split reduction ----
        const float* sw = st->sw;
        float partial = 0.f;

        if (m_case == 0) {
            float a = 0.f;
            #pragma unroll 8
            for (int u = 0; u < 24; u++) a += px1[ub + u] * sw[(ub + u)*48 + m_wI];
            float bb = 0.f;
            #pragma unroll
            for (int u = 0; u < 5; u++) bb += S->d110[vb + u] * sw[2884 + (vb + u)*48 + m_wI];
            partial = a * px2[0] + RS3 * bb;
        } else if (m_case == 1) {
            float t01 = 0.f;
            #pragma unroll 8
            for (int u = 0; u < 24; u++) t01 += px1[ub + u] * sw[2304 + (ub + u)*10 + m_wI];
            float a10 = 0.f, a12 = 0.f, a211 = 0.f;
            #pragma unroll
            for (int u = 0; u < 5; u++) {
                int uu = vb + u;
                a10  += px1[48 + uu*3 + m_k] * sw[2784 + uu*10 + m_wI];
                a12  += S->c12[uu*3 + m_k]   * sw[3464 + uu*10 + m_wI];
                a211 += S->c211[uu*3 + m_k]  * sw[3664 + uu*10 + m_wI];
            }
            partial = RS3 * (t01 * px2[1 + m_k] + px2[0] * a10) + a12 + a211;
        } else if (m_case == 2) {
            float t31 = 0.f;
            #pragma unroll 8
            for (int u = 0; u < 24; u++) t31 += px1[108 + ub + u] * sw[6648 + (ub + u)*10 + m_wI];
            float a112 = 0.f, a20 = 0.f, a22 = 0.f;
            #pragma unroll
            for (int u = 0; u < 5; u++) {
                int uu = vb + u;
                a112 += S->c112[uu*3 + m_k] * sw[3364 + uu*10 + m_wI];
                a20  += px1[78 + uu*3 + m_k] * sw[3564 + uu*10 + m_wI];
                a22  += S->c22[uu*3 + m_k]  * sw[4244 + uu*10 + m_wI];
            }
            partial = a112 + RS3 * (px2[0] * a20 + t31 * px2[1 + m_k]) + a22;
        } else if (m_case == 3) {
            float a = 0.f;
            #pragma unroll
            for (int u = 0; u < 5; u++) a += S->d213[vb + u] * sw[3764 + (vb + u)*48 + m_wI];
            float bb = 0.f;
            #pragma unroll 8
            for (int u = 0; u < 24; u++) bb += px1[108 + ub + u] * sw[4344 + (ub + u)*48 + m_wI];
            partial = RS3 * a + bb * px2[0];
        }

        // combine lane-pair halves (uniform across the full warp)
        float sum = partial + __shfl_xor_sync(0xFFFFFFFFu, partial, 1);

        if (h == 0 && m_case < 4) {
            float* orow = out + row * XW;
            float norm = (m_case == 0) ? NORM_0E
                       : (m_case == 1) ? NORM_1O
                       : (m_case == 2) ? NORM_1E : NORM_0O;
            orow[lt] = norm * sum;
        }

        __syncthreads();   // all reads of stage s complete

        // ---- Reissue stage s for iteration i+2 ----
        if (tid == 0 && i + NSTAGE < cnt)
            issue_stage_tma(S, s, w, x1, (size_t)b + (size_t)(i + NSTAGE) * G);
    }
}

// ---------------------------------------------------------------------------
extern "C" void kernel_launch(void* const* d_in, const int* in_sizes, int n_in,
                              void* d_out, int out_size)
{
    const float* x1 = (const float*)d_in[0];
    const float* x2 = (const float*)d_in[1];
    const float* w  = (const float*)d_in[2];
    float* out = (float*)d_out;

    int B = in_sizes[1] / 9;
    int smem_bytes = (int)sizeof(SmemLayout);

    cudaFuncSetAttribute(tp_kernel,
                         cudaFuncAttributeMaxDynamicSharedMemorySize, smem_bytes);

    init_w3j_kernel<<<1, 128>>>();
    tp_kernel<<<444, 320, smem_bytes>>>(x1, x2, w, out, B);
}

// round 9
// speedup vs baseline: 1.3420x; 1.1337x over previous
#include <cuda_runtime.h>
#include <math.h>
#include <stdint.h>

// ============================================================================
// TPForth: e3nn-style tensor product, B x (x1[156], x2[9], w[7128]) -> out[156]
// One-shot block per row, 160 threads, 28.5KB weight TMA issued at cycle 0.
// __launch_bounds__(160,7): 7 independent block slots per SM -> ~200KB of
// copies in flight per SM, demand gaps smoothed by the HW CTA scheduler.
// ============================================================================

#define WTOT 7128
#define WBYTES (WTOT * 4)
#define XW   156

// Weight sub-matrix offsets (floats within a row), shapes (U, Wd):
//  w00  @    0 (48,48)   w01  @ 2304 (48,10)   w10  @ 2784 (10,10)
//  w110 @ 2884 (10,48)   w112 @ 3364 (10,10)   w12  @ 3464 (10,10)
//  w20  @ 3564 (10,10)   w211 @ 3664 (10,10)   w213 @ 3764 (10,48)
//  w22  @ 4244 (10,10)   w30  @ 4344 (48,48)   w31  @ 6648 (48,10)

__device__ float d_w3j111[27];
__device__ float d_w3j121[45];

// ---------------------------------------------------------------------------
// Parallel fp32 Wigner-3j init (one element per thread).
// ---------------------------------------------------------------------------
struct CF { float r, i; };
__device__ __forceinline__ CF cmulf(CF a, CF b) {
    CF c; c.r = a.r*b.r - a.i*b.i; c.i = a.r*b.i + a.i*b.r; return c;
}

__device__ void change_basis_f(int l, CF* q) {
    int n = 2*l + 1;
    for (int a = 0; a < n*n; a++) { q[a].r = 0.f; q[a].i = 0.f; }
    const float rs2 = 0.70710678118654752f;
    for (int m = -l; m < 0; m++) {
        q[(l+m)*n + (l - m)].r =  rs2;
        q[(l+m)*n + (l + m)].i = -rs2;
    }
    q[l*n + l].r = 1.f;
    for (int m = 1; m <= l; m++) {
        float s = (m & 1) ? -1.f : 1.f;
        q[(l+m)*n + (l+m)].r = s * rs2;
        q[(l+m)*n + (l-m)].i = s * rs2;
    }
    CF ph;
    switch (l & 3) {
        case 0: ph.r = 1;  ph.i = 0;  break;
        case 1: ph.r = 0;  ph.i = -1; break;
        case 2: ph.r = -1; ph.i = 0;  break;
        default: ph.r = 0; ph.i = 1;  break;
    }
    for (int a = 0; a < n*n; a++) q[a] = cmulf(q[a], ph);
}

__device__ float cg_f(int j1, int j2, int j3, int m1, int m2, int m3,
                      const float* ft) {
    int vmin = -j1 + j2 + m3;
    if (-j1 + m1 > vmin) vmin = -j1 + m1;
    if (0 > vmin) vmin = 0;
    int vmax = j2 + j3 + m1;
    if (j3 - j1 + j2 < vmax) vmax = j3 - j1 + j2;
    if (j3 + m3 < vmax) vmax = j3 + m3;
    float C = sqrtf((2.f*j3 + 1.f) * ft[j3+j1-j2] * ft[j3-j1+j2] * ft[j1+j2-j3]
                    * ft[j3+m3] * ft[j3-m3]
                    / (ft[j1+j2+j3+1] * ft[j1-m1] * ft[j1+m1]
                       * ft[j2-m2] * ft[j2+m2]));
    float S = 0.f;
    for (int v = vmin; v <= vmax; v++) {
        float sgn = ((v + j2 + m2) & 1) ? -1.f : 1.f;
        S += sgn * ft[j2+j3+m1-v] * ft[j1-m1+v]
             / (ft[v] * ft[j3-j1+j2-v] * ft[j3+m3-v] * ft[v+j1-j2-m3]);
    }
    return C * S;
}

__device__ float w3j_elem(int l1, int l2, int l3, int j, int l, int m,
                          const float* ft) {
    int n1 = 2*l1+1, n2 = 2*l2+1, n3 = 2*l3+1;
    CF Q1[25], Q2[25], Q3[25];
    change_basis_f(l1, Q1);
    change_basis_f(l2, Q2);
    change_basis_f(l3, Q3);
    float acc = 0.f;
    for (int i = 0; i < n1; i++) {
        for (int k = 0; k < n2; k++) {
            int m3v = (i - l1) + (k - l2);
            if (m3v < -l3 || m3v > l3) continue;
            int nn = l3 + m3v;
            float cgv = cg_f(l1, l2, l3, i - l1, k - l2, m3v, ft);
            CF t = cmulf(Q1[i*n1 + j], Q2[k*n2 + l]);
            CF q3c; q3c.r = Q3[nn*n3 + m].r; q3c.i = -Q3[nn*n3 + m].i;
            t = cmulf(t, q3c);
            acc += t.r * cgv;
        }
    }
    return acc;
}

__global__ void init_w3j_kernel() {
    __shared__ float s111[27], s121[45];
    __shared__ float inv111, inv121;
    int tid = threadIdx.x;
    float ft[8];
    ft[0] = 1.f;
    for (int k = 1; k < 8; k++) ft[k] = ft[k-1] * (float)k;

    if (tid < 27) {
        int j = tid / 9, rem = tid % 9, l = rem / 3, m = rem % 3;
        s111[tid] = w3j_elem(1, 1, 1, j, l, m, ft);
    } else if (tid >= 32 && tid < 77) {
        int idx = tid - 32;
        int j = idx / 15, rem = idx % 15, l = rem / 3, m = rem % 3;
        s121[idx] = w3j_elem(1, 2, 1, j, l, m, ft);
    }
    __syncthreads();
    if (tid == 0) {
        float s = 0.f;
        for (int a = 0; a < 27; a++) s += s111[a] * s111[a];
        inv111 = rsqrtf(s);
    }
    if (tid == 1) {
        float s = 0.f;
        for (int a = 0; a < 45; a++) s += s121[a] * s121[a];
        inv121 = rsqrtf(s);
    }
    __syncthreads();
    if (tid < 27) d_w3j111[tid] = s111[tid] * inv111;
    if (tid >= 32 && tid < 77) d_w3j121[tid - 32] = s121[tid - 32] * inv121;
}

// ---------------------------------------------------------------------------
__device__ __forceinline__ uint32_t smem_u32(const void* p) {
    uint32_t a;
    asm("{ .reg .u64 t; cvta.to.shared.u64 t, %1; cvt.u32.u64 %0, t; }"
        : "=r"(a) : "l"(p));
    return a;
}

struct __align__(128) SmemLayout {
    float sw[WTOT];                 // 28512 B, TMA destination
    float sx1[XW];
    float sx2[12];
    float d110[10], d213[10];
    float c112[30], c12[30], c211[30], c22[30];
    float sj1[27], sj2[45];
    uint64_t mbar;
};

__global__ __launch_bounds__(160, 7) void tp_kernel(
    const float* __restrict__ x1,
    const float* __restrict__ x2,
    const float* __restrict__ w,
    float* __restrict__ out)
{
    extern __shared__ __align__(128) char smem_raw[];
    SmemLayout* S = reinterpret_cast<SmemLayout*>(smem_raw);

    const int tid = threadIdx.x;
    const size_t z = blockIdx.x;

    const uint32_t mbar_a = smem_u32(&S->mbar);

    // ---- tid 0: issue the 28.5KB weight TMA at cycle 0 ----
    if (tid == 0) {
        asm volatile("mbarrier.init.shared.b64 [%0], %1;"
                     :: "r"(mbar_a), "r"(1) : "memory");
        asm volatile("fence.proxy.async.shared::cta;" ::: "memory");
        asm volatile("mbarrier.arrive.expect_tx.shared.b64 _, [%0], %1;"
                     :: "r"(mbar_a), "r"((uint32_t)WBYTES) : "memory");
        asm volatile(
            "cp.async.bulk.shared::cluster.global.mbarrier::complete_tx::bytes "
            "[%0], [%1], %2, [%3];"
            :: "r"(smem_u32(S->sw)), "l"(w + z * WTOT), "r"((uint32_t)WBYTES),
               "r"(mbar_a) : "memory");
    }

    // ---- Small operand loads in parallel with the TMA ----
    if (tid < XW/4)                          // 39 float4: x1
        reinterpret_cast<float4*>(S->sx1)[tid] =
            (reinterpret_cast<const float4*>(x1) + z * (XW/4))[tid];
    else if (tid >= 40 && tid < 49)          // 9 floats: x2
        S->sx2[tid - 40] = x2[z * 9 + (tid - 40)];
    else if (tid >= 64 && tid < 91)          // 27: w3j111
        S->sj1[tid - 64] = d_w3j111[tid - 64];
    else if (tid >= 96 && tid < 141)         // 45: w3j121
        S->sj2[tid - 96] = d_w3j121[tid - 96];
    __syncthreads();   // sx1/sx2/sj ready; mbar init published

    // ---- Aux coefficients (fully under the TMA) ----
    const float* px1 = S->sx1;
    const float* px2 = S->sx2;
    if (tid < 10) {
        float v = 0.f;
        #pragma unroll
        for (int q = 0; q < 3; q++) v += px1[48 + tid*3 + q] * px2[1 + q];
        S->d110[tid] = v;
    } else if (tid < 20) {
        int u = tid - 10; float v = 0.f;
        #pragma unroll
        for (int q = 0; q < 3; q++) v += px1[78 + u*3 + q] * px2[1 + q];
        S->d213[u] = v;
    } else if (tid < 50) {
        int t = tid - 20, u = t/3, k = t%3; float v = 0.f;
        #pragma unroll
        for (int q = 0; q < 3; q++)
            #pragma unroll
            for (int j = 0; j < 3; j++)
                v += px1[48 + u*3 + q] * px2[1 + j] * S->sj1[q*9 + j*3 + k];
        S->c112[t] = v;
    } else if (tid < 80) {
        int t = tid - 50, u = t/3, k = t%3; float v = 0.f;
        #pragma unroll
        for (int q = 0; q < 3; q++)
            #pragma unroll
            for (int j = 0; j < 5; j++)
                v += px1[48 + u*3 + q] * px2[4 + j] * S->sj2[q*15 + j*3 + k];
        S->c12[t] = v;
    } else if (tid < 110) {
        int t = tid - 80, u = t/3, k = t%3; float v = 0.f;
        #pragma unroll
        for (int q = 0; q < 3; q++)
            #pragma unroll
            for (int j = 0; j < 3; j++)
                v += px1[78 + u*3 + q] * px2[1 + j] * S->sj1[q*9 + j*3 + k];
        S->c211[t] = v;
    } else if (tid < 140) {
        int t = tid - 110, u = t/3, k = t%3; float v = 0.f;
        #pragma unroll
        for (int q = 0; q < 3; q++)
            #pragma unroll
            for (int j = 0; j < 5; j++)
                v += px1[78 + u*3 + q] * px2[4 + j] * S->sj2[q*15 + j*3 + k];
        S->c22[t] = v;
    }
    __syncthreads();   // aux ready

    // ---- Wait for weights ----
    {
        uint32_t done;
        do {
            asm volatile(
                "{\n .reg .pred p;\n"
                " mbarrier.try_wait.parity.acquire.cta.shared::cta.b64 p, [%1], %2, 0x989680;\n"
                " selp.b32 %0, 1, 0, p;\n}"
                : "=r"(done) : "r"(mbar_a), "r"(0u) : "memory");
        } while (!done);
    }

    // ---- Main: one thread per output element ----
    const float NORM_0E = 0.13130643285972254f;  // sqrt(1/58)
    const float NORM_1O = 0.19611613513818404f;  // sqrt(3/78)
    const float NORM_1E = 0.19611613513818404f;
    const float NORM_0O = 0.13130643285972254f;
    const float RS3     = 0.57735026918962576f;

    const float* sw = S->sw;
    float* orow = out + z * XW;

    if (tid < 48) {
        // r0e[w]
        int wI = tid;
        float a = 0.f;
        #pragma unroll 8
        for (int u = 0; u < 48; u++) a += px1[u] * sw[u*48 + wI];
        float b = 0.f;
        #pragma unroll
        for (int u = 0; u < 10; u++) b += S->d110[u] * sw[2884 + u*48 + wI];
        orow[wI] = NORM_0E * (a * px2[0] + RS3 * b);
    } else if (tid < 78) {
        // r1o[w,i]
        int t = tid - 48, wI = t/3, i = t%3;
        float t01 = 0.f;
        #pragma unroll 8
        for (int u = 0; u < 48; u++) t01 += px1[u] * sw[2304 + u*10 + wI];
        float a10 = 0.f, a12 = 0.f, a211 = 0.f;
        #pragma unroll
        for (int u = 0; u < 10; u++) {
            a10  += px1[48 + u*3 + i] * sw[2784 + u*10 + wI];
            a12  += S->c12[u*3 + i]   * sw[3464 + u*10 + wI];
            a211 += S->c211[u*3 + i]  * sw[3664 + u*10 + wI];
        }
        orow[48 + wI*3 + i] =
            NORM_1O * (RS3 * (t01 * px2[1 + i] + px2[0] * a10) + a12 + a211);
    } else if (tid < 108) {
        // r1e[w,k]
        int t = tid - 78, wI = t/3, k = t%3;
        float t31 = 0.f;
        #pragma unroll 8
        for (int u = 0; u < 48; u++) t31 += px1[108 + u] * sw[6648 + u*10 + wI];
        float a112 = 0.f, a20 = 0.f, a22 = 0.f;
        #pragma unroll
        for (int u = 0; u < 10; u++) {
            a112 += S->c112[u*3 + k]  * sw[3364 + u*10 + wI];
            a20  += px1[78 + u*3 + k] * sw[3564 + u*10 + wI];
            a22  += S->c22[u*3 + k]   * sw[4244 + u*10 + wI];
        }
        orow[78 + wI*3 + k] =
            NORM_1E * (a112 + RS3 * (px2[0] * a20 + t31 * px2[1 + k]) + a22);
    } else if (tid < 156) {
        // r0o[w]
        int wI = tid - 108;
        float a = 0.f;
        #pragma unroll
        for (int u = 0; u < 10; u++) a += S->d213[u] * sw[3764 + u*48 + wI];
        float b = 0.f;
        #pragma unroll 8
        for (int u = 0; u < 48; u++) b += px1[108 + u] * sw[4344 + u*48 + wI];
        orow[108 + wI] = NORM_0O * (RS3 * a + b * px2[0]);
    }
}

// ---------------------------------------------------------------------------
extern "C" void kernel_launch(void* const* d_in, const int* in_sizes, int n_in,
                              void* d_out, int out_size)
{
    const float* x1 = (const float*)d_in[0];
    const float* x2 = (const float*)d_in[1];
    const float* w  = (const float*)d_in[2];
    float* out = (float*)d_out;

    int B = in_sizes[1] / 9;   // x2 has 9 floats per row
    int smem_bytes = (int)sizeof(SmemLayout);

    cudaFuncSetAttribute(tp_kernel,
                         cudaFuncAttributeMaxDynamicSharedMemorySize, smem_bytes);

    init_w3j_kernel<<<1, 128>>>();
    tp_kernel<<<B, 160, smem_bytes>>>(x1, x2, w, out);
}

// round 10
// speedup vs baseline: 1.3668x; 1.0185x over previous
#include <cuda_runtime.h>
#include <math.h>
#include <stdint.h>

// ============================================================================
// TPForth: e3nn-style tensor product, B x (x1[156], x2[9], w[7128]) -> out[156]
// TWO 96-thread half-blocks per row (grid 2B). Type A computes {r0e,r1o},
// type B computes {r1e,r0o}; each TMAs exactly its 3564-float weight half
// (3 contiguous bulk copies, zero duplication). ~15.3KB smem -> 14 slots/SM.
// ============================================================================

#define WTOT  7128
#define WHALF 3564
#define XW    156

// Global weight offsets (floats): w00@0(48x48) w01@2304(48x10) w10@2784(10x10)
// w110@2884(10x48) w112@3364(10x10) w12@3464(10x10) w20@3564(10x10)
// w211@3664(10x10) w213@3764(10x48) w22@4244(10x10) w30@4344(48x48) w31@6648(48x10)
//
// Type A copies [0,3364)+[3464,3564)+[3664,3764) -> local w00@0 w01@2304
//   w10@2784 w110@2884 w12@3364 w211@3464
// Type B copies [3364,3464)+[3564,3664)+[3764,7128) -> local w112@0 w20@100
//   w213@200 w22@680 w30@780 w31@3084

__device__ float d_w3j111[27];
__device__ float d_w3j121[45];

// ---------------------------------------------------------------------------
// Parallel fp32 Wigner-3j init (one element per thread).
// ---------------------------------------------------------------------------
struct CF { float r, i; };
__device__ __forceinline__ CF cmulf(CF a, CF b) {
    CF c; c.r = a.r*b.r - a.i*b.i; c.i = a.r*b.i + a.i*b.r; return c;
}

__device__ void change_basis_f(int l, CF* q) {
    int n = 2*l + 1;
    for (int a = 0; a < n*n; a++) { q[a].r = 0.f; q[a].i = 0.f; }
    const float rs2 = 0.70710678118654752f;
    for (int m = -l; m < 0; m++) {
        q[(l+m)*n + (l - m)].r =  rs2;
        q[(l+m)*n + (l + m)].i = -rs2;
    }
    q[l*n + l].r = 1.f;
    for (int m = 1; m <= l; m++) {
        float s = (m & 1) ? -1.f : 1.f;
        q[(l+m)*n + (l+m)].r = s * rs2;
        q[(l+m)*n + (l-m)].i = s * rs2;
    }
    CF ph;
    switch (l & 3) {
        case 0: ph.r = 1;  ph.i = 0;  break;
        case 1: ph.r = 0;  ph.i = -1; break;
        case 2: ph.r = -1; ph.i = 0;  break;
        default: ph.r = 0; ph.i = 1;  break;
    }
    for (int a = 0; a < n*n; a++) q[a] = cmulf(q[a], ph);
}

__device__ float cg_f(int j1, int j2, int j3, int m1, int m2, int m3,
                      const float* ft) {
    int vmin = -j1 + j2 + m3;
    if (-j1 + m1 > vmin) vmin = -j1 + m1;
    if (0 > vmin) vmin = 0;
    int vmax = j2 + j3 + m1;
    if (j3 - j1 + j2 < vmax) vmax = j3 - j1 + j2;
    if (j3 + m3 < vmax) vmax = j3 + m3;
    float C = sqrtf((2.f*j3 + 1.f) * ft[j3+j1-j2] * ft[j3-j1+j2] * ft[j1+j2-j3]
                    * ft[j3+m3] * ft[j3-m3]
                    / (ft[j1+j2+j3+1] * ft[j1-m1] * ft[j1+m1]
                       * ft[j2-m2] * ft[j2+m2]));
    float S = 0.f;
    for (int v = vmin; v <= vmax; v++) {
        float sgn = ((v + j2 + m2) & 1) ? -1.f : 1.f;
        S += sgn * ft[j2+j3+m1-v] * ft[j1-m1+v]
             / (ft[v] * ft[j3-j1+j2-v] * ft[j3+m3-v] * ft[v+j1-j2-m3]);
    }
    return C * S;
}

__device__ float w3j_elem(int l1, int l2, int l3, int j, int l, int m,
                          const float* ft) {
    int n1 = 2*l1+1, n2 = 2*l2+1, n3 = 2*l3+1;
    CF Q1[25], Q2[25], Q3[25];
    change_basis_f(l1, Q1);
    change_basis_f(l2, Q2);
    change_basis_f(l3, Q3);
    float acc = 0.f;
    for (int i = 0; i < n1; i++) {
        for (int k = 0; k < n2; k++) {
            int m3v = (i - l1) + (k - l2);
            if (m3v < -l3 || m3v > l3) continue;
            int nn = l3 + m3v;
            float cgv = cg_f(l1, l2, l3, i - l1, k - l2, m3v, ft);
            CF t = cmulf(Q1[i*n1 + j], Q2[k*n2 + l]);
            CF q3c; q3c.r = Q3[nn*n3 + m].r; q3c.i = -Q3[nn*n3 + m].i;
            t = cmulf(t, q3c);
            acc += t.r * cgv;
        }
    }
    return acc;
}

__global__ void init_w3j_kernel() {
    __shared__ float s111[27], s121[45];
    __shared__ float inv111, inv121;
    int tid = threadIdx.x;
    float ft[8];
    ft[0] = 1.f;
    for (int k = 1; k < 8; k++) ft[k] = ft[k-1] * (float)k;

    if (tid < 27) {
        int j = tid / 9, rem = tid % 9, l = rem / 3, m = rem % 3;
        s111[tid] = w3j_elem(1, 1, 1, j, l, m, ft);
    } else if (tid >= 32 && tid < 77) {
        int idx = tid - 32;
        int j = idx / 15, rem = idx % 15, l = rem / 3, m = rem % 3;
        s121[idx] = w3j_elem(1, 2, 1, j, l, m, ft);
    }
    __syncthreads();
    if (tid == 0) {
        float s = 0.f;
        for (int a = 0; a < 27; a++) s += s111[a] * s111[a];
        inv111 = rsqrtf(s);
    }
    if (tid == 1) {
        float s = 0.f;
        for (int a = 0; a < 45; a++) s += s121[a] * s121[a];
        inv121 = rsqrtf(s);
    }
    __syncthreads();
    if (tid < 27) d_w3j111[tid] = s111[tid] * inv111;
    if (tid >= 32 && tid < 77) d_w3j121[tid - 32] = s121[tid - 32] * inv121;
}

// ---------------------------------------------------------------------------
__device__ __forceinline__ uint32_t smem_u32(const void* p) {
    uint32_t a;
    asm("{ .reg .u64 t; cvta.to.shared.u64 t, %1; cvt.u32.u64 %0, t; }"
        : "=r"(a) : "l"(p));
    return a;
}

__device__ __forceinline__ void bulk_cp(uint32_t dst, const float* src,
                                        uint32_t bytes, uint32_t mb) {
    asm volatile(
        "cp.async.bulk.shared::cluster.global.mbarrier::complete_tx::bytes "
        "[%0], [%1], %2, [%3];"
        :: "r"(dst), "l"(src), "r"(bytes), "r"(mb) : "memory");
}

struct __align__(128) SmemLayout {
    float sw[WHALF];                // 14256 B, TMA destination
    float sx1[108];
    float sx2[12];
    float da[10];                   // A: d110   B: d213
    float ca[30];                   // A: c12    B: c112
    float cb[32];                   // A: c211   B: c22
    float sj1[27], sj2[45];
    uint64_t mbar;
};

__global__ __launch_bounds__(96, 14) void tp_kernel(
    const float* __restrict__ x1,
    const float* __restrict__ x2,
    const float* __restrict__ w,
    float* __restrict__ out)
{
    extern __shared__ __align__(128) char smem_raw[];
    SmemLayout* S = reinterpret_cast<SmemLayout*>(smem_raw);

    const int tid = threadIdx.x;
    const size_t z = (size_t)(blockIdx.x >> 1);
    const bool isA = (blockIdx.x & 1u) == 0u;

    const uint32_t mbar_a = smem_u32(&S->mbar);
    const float* wrow = w + z * WTOT;

    // ---- tid 0: issue this half's 3 bulk copies at cycle 0 ----
    if (tid == 0) {
        asm volatile("mbarrier.init.shared.b64 [%0], %1;"
                     :: "r"(mbar_a), "r"(1) : "memory");
        asm volatile("fence.proxy.async.shared::cta;" ::: "memory");
        asm volatile("mbarrier.arrive.expect_tx.shared.b64 _, [%0], %1;"
                     :: "r"(mbar_a), "r"((uint32_t)(WHALF * 4)) : "memory");
        uint32_t sws = smem_u32(S->sw);
        if (isA) {
            bulk_cp(sws,             wrow,        3364u * 4u, mbar_a);
            bulk_cp(sws + 3364u*4u,  wrow + 3464,  100u * 4u, mbar_a);
            bulk_cp(sws + 3464u*4u,  wrow + 3664,  100u * 4u, mbar_a);
        } else {
            bulk_cp(sws,             wrow + 3364,  100u * 4u, mbar_a);
            bulk_cp(sws +  100u*4u,  wrow + 3564,  100u * 4u, mbar_a);
            bulk_cp(sws +  200u*4u,  wrow + 3764, 3364u * 4u, mbar_a);
        }
    }

    // ---- Small operand loads in parallel with the TMA ----
    // A keeps x1[0:108) (0e,1o,1e); B keeps x1[48:156) (1o,1e,0o).
    if (tid < 27) {
        const float4* src = reinterpret_cast<const float4*>(x1)
                          + (z * XW + (isA ? 0 : 48)) / 4;
        reinterpret_cast<float4*>(S->sx1)[tid] = src[tid];
    } else if (tid >= 32 && tid < 41) {
        S->sx2[tid - 32] = x2[z * 9 + (tid - 32)];
    }
    if (tid >= 48 && tid < 75)  S->sj1[tid - 48] = d_w3j111[tid - 48];
    if (tid >= 48 && tid < 93)  S->sj2[tid - 48] = d_w3j121[tid - 48];
    __syncthreads();

    const float* px1 = S->sx1;
    const float* px2 = S->sx2;

    // ---- Aux coefficients (under the TMA) ----
    // A: da=d110(x1_1o.x2_1o) ca=c12(x1_1o ox x2_2e) cb=c211(x1_1e ox x2_1o)
    // B: da=d213(x1_1e.x2_1o) ca=c112(x1_1o ox x2_1o) cb=c22(x1_1e ox x2_2e)
    if (tid < 10) {
        const float* p = isA ? (px1 + 48) : (px1 + 30);   // 1o vs 1e base
        float v = 0.f;
        #pragma unroll
        for (int q = 0; q < 3; q++) v += p[tid*3 + q] * px2[1 + q];
        S->da[tid] = v;
    } else if (tid < 40) {
        int t = tid - 10, u = t/3, k = t%3; float v = 0.f;
        if (isA) {      // c12: x1_1o @48, x2_2e, sj2
            #pragma unroll
            for (int q = 0; q < 3; q++)
                #pragma unroll
                for (int j = 0; j < 5; j++)
                    v += px1[48 + u*3 + q] * px2[4 + j] * S->sj2[q*15 + j*3 + k];
        } else {        // c112: x1_1o @0, x2_1o, sj1
            #pragma unroll
            for (int q = 0; q < 3; q++)
                #pragma unroll
                for (int j = 0; j < 3; j++)
                    v += px1[u*3 + q] * px2[1 + j] * S->sj1[q*9 + j*3 + k];
        }
        S->ca[t] = v;
    } else if (tid < 70) {
        int t = tid - 40, u = t/3, k = t%3; float v = 0.f;
        if (isA) {      // c211: x1_1e @78, x2_1o, sj1
            #pragma unroll
            for (int q = 0; q < 3; q++)
                #pragma unroll
                for (int j = 0; j < 3; j++)
                    v += px1[78 + u*3 + q] * px2[1 + j] * S->sj1[q*9 + j*3 + k];
        } else {        // c22: x1_1e @30, x2_2e, sj2
            #pragma unroll
            for (int q = 0; q < 3; q++)
                #pragma unroll
                for (int j = 0; j < 5; j++)
                    v += px1[30 + u*3 + q] * px2[4 + j] * S->sj2[q*15 + j*3 + k];
        }
        S->cb[t] = v;
    }
    __syncthreads();

    // ---- Wait for weights ----
    {
        uint32_t done;
        do {
            asm volatile(
                "{\n .reg .pred p;\n"
                " mbarrier.try_wait.parity.acquire.cta.shared::cta.b64 p, [%1], %2, 0x989680;\n"
                " selp.b32 %0, 1, 0, p;\n}"
                : "=r"(done) : "r"(mbar_a), "r"(0u) : "memory");
        } while (!done);
    }

    const float NORM_0E = 0.13130643285972254f;  // sqrt(1/58)
    const float NORM_1O = 0.19611613513818404f;  // sqrt(3/78)
    const float NORM_1E = 0.19611613513818404f;
    const float NORM_0O = 0.13130643285972254f;
    const float RS3     = 0.57735026918962576f;

    const float* sw = S->sw;
    float* orow = out + z * XW;

    if (isA) {
        if (tid < 48) {
            // r0e[w]: w00@0, w110@2884
            float a = 0.f;
            #pragma unroll 8
            for (int u = 0; u < 48; u++) a += px1[u] * sw[u*48 + tid];
            float bb = 0.f;
            #pragma unroll
            for (int u = 0; u < 10; u++) bb += S->da[u] * sw[2884 + u*48 + tid];
            orow[tid] = NORM_0E * (a * px2[0] + RS3 * bb);
        } else if (tid < 78) {
            // r1o[w,i]: w01@2304, w10@2784, w12@3364(local), w211@3464(local)
            int t = tid - 48, wI = t/3, i = t%3;
            float t01 = 0.f;
            #pragma unroll 8
            for (int u = 0; u < 48; u++) t01 += px1[u] * sw[2304 + u*10 + wI];
            float a10 = 0.f, a12 = 0.f, a211 = 0.f;
            #pragma unroll
            for (int u = 0; u < 10; u++) {
                a10  += px1[48 + u*3 + i] * sw[2784 + u*10 + wI];
                a12  += S->ca[u*3 + i]    * sw[3364 + u*10 + wI];
                a211 += S->cb[u*3 + i]    * sw[3464 + u*10 + wI];
            }
            orow[48 + wI*3 + i] =
                NORM_1O * (RS3 * (t01 * px2[1 + i] + px2[0] * a10) + a12 + a211);
        }
    } else {
        if (tid < 30) {
            // r1e[w,k]: w112@0, w20@100, w22@680, w31@3084 (local)
            int wI = tid/3, k = tid%3;
            float t31 = 0.f;
            #pragma unroll 8
            for (int u = 0; u < 48; u++) t31 += px1[60 + u] * sw[3084 + u*10 + wI];
            float a112 = 0.f, a20 = 0.f, a22 = 0.f;
            #pragma unroll
            for (int u = 0; u < 10; u++) {
                a112 += S->ca[u*3 + k]    * sw[u*10 + wI];
                a20  += px1[30 + u*3 + k] * sw[100 + u*10 + wI];
                a22  += S->cb[u*3 + k]    * sw[680 + u*10 + wI];
            }
            orow[78 + wI*3 + k] =
                NORM_1E * (a112 + RS3 * (px2[0] * a20 + t31 * px2[1 + k]) + a22);
        } else if (tid < 78) {
            // r0o[w]: w213@200, w30@780 (local); x1_0o @ px1[60]
            int wI = tid - 30;
            float a = 0.f;
            #pragma unroll
            for (int u = 0; u < 10; u++) a += S->da[u] * sw[200 + u*48 + wI];
            float bb = 0.f;
            #pragma unroll 8
            for (int u = 0; u < 48; u++) bb += px1[60 + u] * sw[780 + u*48 + wI];
            orow[108 + wI] = NORM_0O * (RS3 * a + bb * px2[0]);
        }
    }
}

// ---------------------------------------------------------------------------
extern "C" void kernel_launch(void* const* d_in, const int* in_sizes, int n_in,
                              void* d_out, int out_size)
{
    const float* x1 = (const float*)d_in[0];
    const float* x2 = (const float*)d_in[1];
    const float* w  = (const float*)d_in[2];
    float* out = (float*)d_out;

    int B = in_sizes[1] / 9;   // x2 has 9 floats per row
    int smem_bytes = (int)sizeof(SmemLayout);

    cudaFuncSetAttribute(tp_kernel,
                         cudaFuncAttributeMaxDynamicSharedMemorySize, smem_bytes);

    init_w3j_kernel<<<1, 128>>>();
    tp_kernel<<<2 * B, 96, smem_bytes>>>(x1, x2, w, out);
}